// round 6
// baseline (speedup 1.0000x reference)
#include <cuda_runtime.h>
#include <cuda_fp16.h>

// RoIMaskAlign via NHWC-fp16 staging, round 6.
// features (B=2, C=256, H=200, W=272) fp32, rois (K, 5) fp32
// out (K, C, 14, 14) fp32
// PH=PW=14, SPATIAL_SCALE=0.25, SR=2, SPATIAL_SHIFT=0, HALF_PART=0, ROI_SCALE=1.2

#define PH 14
#define PW 14

static constexpr int   Bc = 2;
static constexpr int   Cc = 256;
static constexpr int   Hc = 200;
static constexpr int   Wc = 272;
static constexpr float SCALE     = 0.25f;
static constexpr float ROI_SCALE = 1.2f;

// NHWC fp16 scratch: (B, H, W, C) = 2*200*272*256 halves = 55.7 MB
__device__ __align__(16) __half g_nhwc[(size_t)Bc * Hc * Wc * Cc];

// ---------------------------------------------------------------------------
// Kernel 1: NCHW fp32 -> NHWC fp16 transpose (unchanged from R5).
// ---------------------------------------------------------------------------
__global__ __launch_bounds__(256)
void transpose_kernel(const float* __restrict__ feat)
{
    __shared__ __align__(16) __half s[16][264];   // [x][c], padded rows

    int x0 = blockIdx.x * 16;
    int y  = blockIdx.y;
    int b  = blockIdx.z;
    int tid = threadIdx.x;
    int xl = tid & 15;
    int ci = tid >> 4;

    const float* fp = feat + (((size_t)b * Cc) * Hc + y) * Wc + x0 + xl;
    #pragma unroll
    for (int k = 0; k < 16; k++) {
        int c = k * 16 + ci;
        s[xl][c] = __float2half_rn(__ldg(fp + (size_t)c * (Hc * Wc)));
    }
    __syncthreads();

    __half* op = g_nhwc + (((size_t)b * Hc + y) * Wc + x0) * Cc;
    #pragma unroll
    for (int j = 0; j < 2; j++) {
        int u = tid + j * 256;
        int x = u >> 5;
        int k = u & 31;
        *reinterpret_cast<uint4*>(op + (size_t)x * Cc + k * 8) =
            *reinterpret_cast<const uint4*>(&s[x][k * 8]);
    }
}

// ---------------------------------------------------------------------------
// Kernel 2: gather. Block = (n, ph); 14 warps, warp = pw.
// Lane owns channels 8*lane..8*lane+7 (one uint4 = 8 fp16 per tap).
// 4 tap loads per bilinear sample are batched for MLP; validity branch is
// warp-uniform.
// ---------------------------------------------------------------------------
__global__ __launch_bounds__(448, 3)
void gather_kernel(const float* __restrict__ rois,
                   float* __restrict__ out)
{
    __shared__ __align__(16) float s[PW][264];   // [pw][c], padded

    int n  = blockIdx.x;
    int ph = blockIdx.y;
    int pw   = threadIdx.x >> 5;   // 0..13
    int lane = threadIdx.x & 31;

    // ---- ROI geometry (identical across the warp) ----
    const float* r = rois + n * 5;
    int   b  = (int)r[0];
    float rx1 = r[1], ry1 = r[2], rx2 = r[3], ry2 = r[4];

    float cx = (rx1 + rx2) * 0.5f;
    float cy = (ry1 + ry2) * 0.5f;
    float rw = (rx2 - rx1) * ROI_SCALE;
    float rh = (ry2 - ry1) * ROI_SCALE;
    float x1s = (cx - 0.5f * rw) * SCALE;
    float x2s = (cx + 0.5f * rw) * SCALE;
    float y1s = (cy - 0.5f * rh) * SCALE;
    float y2s = (cy + 0.5f * rh) * SCALE;

    float roi_w = fmaxf(x2s - x1s, 1.0f);
    float roi_h = fmaxf(y2s - y1s, 1.0f);
    float bin_w = roi_w * (1.0f / PW);
    float bin_h = roi_h * (1.0f / PH);

    const __half* tb = g_nhwc;

    float a0=0.f,a1=0.f,a2=0.f,a3=0.f,a4=0.f,a5=0.f,a6=0.f,a7=0.f;

    // per-sample x data (shared across sy)
    int   xi0[2], xi1[2];
    float lx[2], hx[2];
    bool  vx[2];
    #pragma unroll
    for (int sx = 0; sx < 2; sx++) {
        float x = x1s + ((float)pw + ((float)sx + 0.5f) * 0.5f) * bin_w;
        vx[sx] = (x > -1.0f) && (x < (float)Wc);
        float xc = fminf(fmaxf(x, 0.0f), (float)(Wc - 1));
        int x0 = (int)floorf(xc);
        xi0[sx] = x0;
        xi1[sx] = min(x0 + 1, Wc - 1);
        lx[sx] = xc - (float)x0;
        hx[sx] = 1.0f - lx[sx];
    }

    #pragma unroll
    for (int sy = 0; sy < 2; sy++) {
        float y = y1s + ((float)ph + (sy ? 0.75f : 0.25f)) * bin_h;
        bool vy = (y > -1.0f) && (y < (float)Hc);
        float yc = fminf(fmaxf(y, 0.0f), (float)(Hc - 1));
        int y0 = (int)floorf(yc);
        int y1b = min(y0 + 1, Hc - 1);
        float ly = yc - (float)y0;
        float hy = 1.0f - ly;

        int rb0 = (b * Hc + y0)  * Wc;
        int rb1 = (b * Hc + y1b) * Wc;

        #pragma unroll
        for (int sx = 0; sx < 2; sx++) {
            if (vy && vx[sx]) {              // warp-uniform branch
                float w00 = hy * hx[sx];
                float w01 = hy * lx[sx];
                float w10 = ly * hx[sx];
                float w11 = ly * lx[sx];

                size_t off = (size_t)lane * 8;
                const uint4* p00 = (const uint4*)(tb + (((size_t)(rb0 + xi0[sx])) << 8) + off);
                const uint4* p01 = (const uint4*)(tb + (((size_t)(rb0 + xi1[sx])) << 8) + off);
                const uint4* p10 = (const uint4*)(tb + (((size_t)(rb1 + xi0[sx])) << 8) + off);
                const uint4* p11 = (const uint4*)(tb + (((size_t)(rb1 + xi1[sx])) << 8) + off);

                // batched loads -> MLP = 4
                uint4 v00 = __ldg(p00);
                uint4 v01 = __ldg(p01);
                uint4 v10 = __ldg(p10);
                uint4 v11 = __ldg(p11);

                const __half2* h00 = (const __half2*)&v00;
                const __half2* h01 = (const __half2*)&v01;
                const __half2* h10 = (const __half2*)&v10;
                const __half2* h11 = (const __half2*)&v11;

                #pragma unroll
                for (int q = 0; q < 4; q++) {
                    float2 f00 = __half22float2(h00[q]);
                    float2 f01 = __half22float2(h01[q]);
                    float2 f10 = __half22float2(h10[q]);
                    float2 f11 = __half22float2(h11[q]);
                    float vx0 = w00 * f00.x + w01 * f01.x + w10 * f10.x + w11 * f11.x;
                    float vx1 = w00 * f00.y + w01 * f01.y + w10 * f10.y + w11 * f11.y;
                    switch (q) {
                        case 0: a0 += vx0; a1 += vx1; break;
                        case 1: a2 += vx0; a3 += vx1; break;
                        case 2: a4 += vx0; a5 += vx1; break;
                        case 3: a6 += vx0; a7 += vx1; break;
                    }
                }
            }
        }
    }

    // mean over 4 samples; stash as (pw, c)
    *reinterpret_cast<float4*>(&s[pw][lane * 8]) =
        make_float4(a0 * 0.25f, a1 * 0.25f, a2 * 0.25f, a3 * 0.25f);
    *reinterpret_cast<float4*>(&s[pw][lane * 8 + 4]) =
        make_float4(a4 * 0.25f, a5 * 0.25f, a6 * 0.25f, a7 * 0.25f);

    __syncthreads();

    // out[(n*C + c)*196 + ph*14 + pw]: 14-float run per (n,c,ph)
    for (int c = threadIdx.x; c < Cc; c += 448) {
        size_t o = ((size_t)n * Cc + c) * (PH * PW) + ph * PW;
        #pragma unroll
        for (int p = 0; p < 7; p++) {
            *reinterpret_cast<float2*>(out + o + 2 * p) =
                make_float2(s[2 * p][c], s[2 * p + 1][c]);
        }
    }
}

extern "C" void kernel_launch(void* const* d_in, const int* in_sizes, int n_in,
                              void* d_out, int out_size)
{
    const float* feat = (const float*)d_in[0];
    const float* rois = (const float*)d_in[1];
    float* out = (float*)d_out;

    int K = in_sizes[1] / 5;

    dim3 tg(Wc / 16, Hc, Bc);          // 17 x 200 x 2
    transpose_kernel<<<tg, 256>>>(feat);

    dim3 gg(K, PH);                    // K x 14
    gather_kernel<<<gg, 448>>>(rois, out);
}